// round 5
// baseline (speedup 1.0000x reference)
#include <cuda_runtime.h>
#include <math.h>

#define BB 256
#define LL 200
#define NN 256
#define DD 16
#define KSUB 8

// Output layout: xhat | mu | logvar | z_traj | zdiff  (all float32)
#define OFF_XHAT 0
#define OFF_MU   (BB*LL*NN)
#define OFF_LV   (OFF_MU + BB*DD)
#define OFF_ZT   (OFF_LV + BB*DD)
#define OFF_ZD   (OFF_ZT + BB*LL*DD)

// decoder intermediate g2: 51200 x 512 fp32
__device__ float g_g2[51200 * 512];

__device__ __forceinline__ float siluf(float x) {
    return __fdividef(x, 1.f + __expf(-x));
}

__device__ __forceinline__ unsigned long long pack2(float lo, float hi) {
    unsigned long long r;
    asm("mov.b64 %0, {%1, %2};" : "=l"(r) : "f"(lo), "f"(hi));
    return r;
}

#define FFMA2(acc, a, b) \
    asm("fma.rn.f32x2 %0, %1, %2, %0;" : "+l"(acc) : "l"(a), "l"(b))

// ---------------------------------------------------------------------------
// Encoder: one CTA per batch row, 256 threads.
// ---------------------------------------------------------------------------
__global__ void __launch_bounds__(256)
enc_kernel(const float* __restrict__ x_seq,
           const float* __restrict__ eps,
           const float* __restrict__ w1, const float* __restrict__ b1,
           const float* __restrict__ w2, const float* __restrict__ b2,
           const float* __restrict__ w3, const float* __restrict__ b3,
           const float* __restrict__ muw, const float* __restrict__ mub,
           const float* __restrict__ lvw, const float* __restrict__ lvb,
           float* __restrict__ out)
{
    __shared__ float x0[256];
    __shared__ float h1[512];
    __shared__ float h2[256];
    __shared__ float h3[128];
    const int b = blockIdx.x;
    const int t = threadIdx.x;

    x0[t] = x_seq[(size_t)b * (LL * NN) + t];
    __syncthreads();

    for (int c = t; c < 512; c += 256) {
        float acc = b1[c];
#pragma unroll 8
        for (int j = 0; j < 256; j++) acc = fmaf(x0[j], w1[j * 512 + c], acc);
        h1[c] = fmaxf(acc, 0.f);
    }
    __syncthreads();

    {
        float acc = b2[t];
#pragma unroll 8
        for (int j = 0; j < 512; j++) acc = fmaf(h1[j], w2[j * 256 + t], acc);
        h2[t] = fmaxf(acc, 0.f);
    }
    __syncthreads();

    if (t < 128) {
        float acc = b3[t];
#pragma unroll 8
        for (int j = 0; j < 256; j++) acc = fmaf(h2[j], w3[j * 128 + t], acc);
        h3[t] = fmaxf(acc, 0.f);
    }
    __syncthreads();

    if (t < 16) {
        float m = mub[t];
        float lv = lvb[t];
#pragma unroll 8
        for (int j = 0; j < 128; j++) {
            m  = fmaf(h3[j], muw[j * 16 + t], m);
            lv = fmaf(h3[j], lvw[j * 16 + t], lv);
        }
        out[OFF_MU + b * DD + t] = m;
        out[OFF_LV + b * DD + t] = lv;
        float z0 = m + expf(0.5f * lv) * eps[b * DD + t];
        out[OFF_ZT + (size_t)b * (LL * DD) + t] = z0;
    }
}

// ---------------------------------------------------------------------------
// ODE integrator v3: one CTA per batch row, 256 threads, 4-phase stages,
// minimal shfls. State (z, k1..k5) lives only in lanes 0-15; zin passed
// through smem; LN computed shfl-free via LDS broadcast.
// ---------------------------------------------------------------------------
__global__ void __launch_bounds__(256, 2)
ode_kernel(const float* __restrict__ tvec,
           const float* __restrict__ w1, const float* __restrict__ b1,
           const float* __restrict__ w2, const float* __restrict__ b2,
           const float* __restrict__ w3, const float* __restrict__ b3,
           const float* __restrict__ lng, const float* __restrict__ lnb,
           float* __restrict__ out)
{
    const int t  = threadIdx.x;
    const int b  = blockIdx.x;

    __shared__ __align__(16) float zins[16];
    __shared__ __align__(16) float h1s[128];
    __shared__ __align__(16) float a2p[192];   // idx = j + 4*(j>>3)
    __shared__ __align__(16) float dzs[16];
    __shared__ float tvs[LL];

    // ---- Layer-2 weights: column c2 = t>>1, half hh = t&1 (64 j's packed) ----
    const int c2 = t >> 1, hh = t & 1;
    unsigned long long w2h[32];
    {
        const int j0 = 64 * hh;
#pragma unroll
        for (int m = 0; m < 32; m++) {
            const int j = j0 + 2 * m;
            w2h[m] = pack2(w2[j * 128 + c2], w2[(j + 1) * 128 + c2]);
        }
    }
    const float b2c = b2[c2];

    // ---- Layer-1 + Layer-3 weights (t<128 only) ----
    const int oo = t >> 3, gg = t & 7;   // L3: 16 outputs x 8 partial threads
    float w1c[16];
    unsigned long long w3p[8];
    float b1t = 0.f, b3o = 0.f;
    if (t < 128) {
#pragma unroll
        for (int j = 0; j < 16; j++) w1c[j] = w1[j * 128 + t];
        b1t = b1[t];
#pragma unroll
        for (int i = 0; i < 8; i++) {
            const int j = gg * 16 + 2 * i;
            w3p[i] = pack2(w3[j * 16 + oo], w3[(j + 1) * 16 + oo]);
        }
        b3o = b3[oo];
    }

    // ---- state lanes (t<16) ----
    float* zrow = out + OFF_ZT + (size_t)b * (LL * DD);
    float zc = 0.f, lgv = 0.f, lbv = 0.f;
    float k1 = 0.f, k2 = 0.f, k3 = 0.f, k4 = 0.f, k5 = 0.f;
    if (t < 16) {
        lgv = lng[t];
        lbv = lnb[t];
        zc  = zrow[t];
        zins[t] = zc;
    }
    for (int i = t; i < LL; i += 256) tvs[i] = tvec[i];
    __syncthreads();

    const unsigned sm32   = (unsigned)__cvta_generic_to_shared(h1s);
    const unsigned hread  = sm32 + 256u * (unsigned)hh;           // h1 half base
    const unsigned a2b    = (unsigned)__cvta_generic_to_shared(a2p);
    const unsigned a3base = a2b + 96u * (unsigned)gg;             // 24*gg floats

    for (int iv = 0; iv < LL - 1; iv++) {
        float hs = 0.f;
        if (t < 16) hs = (tvs[iv + 1] - tvs[iv]) * (1.f / (float)KSUB);

        for (int sub = 0; sub < KSUB; sub++) {
#pragma unroll
            for (int s = 0; s < 6; s++) {
                // ---------- L1: warps 0-3, zin from smem ----------
                if (t < 128) {
                    const float4 za = ((const float4*)zins)[0];
                    const float4 zbv = ((const float4*)zins)[1];
                    const float4 zcv = ((const float4*)zins)[2];
                    const float4 zdv = ((const float4*)zins)[3];
                    float a0 = fmaf(za.x,  w1c[0],  b1t);
                    float a1 = za.y  * w1c[1];
                    float a2 = za.z  * w1c[2];
                    float a3 = za.w  * w1c[3];
                    a0 = fmaf(zbv.x, w1c[4],  a0);
                    a1 = fmaf(zbv.y, w1c[5],  a1);
                    a2 = fmaf(zbv.z, w1c[6],  a2);
                    a3 = fmaf(zbv.w, w1c[7],  a3);
                    a0 = fmaf(zcv.x, w1c[8],  a0);
                    a1 = fmaf(zcv.y, w1c[9],  a1);
                    a2 = fmaf(zcv.z, w1c[10], a2);
                    a3 = fmaf(zcv.w, w1c[11], a3);
                    a0 = fmaf(zdv.x, w1c[12], a0);
                    a1 = fmaf(zdv.y, w1c[13], a1);
                    a2 = fmaf(zdv.z, w1c[14], a2);
                    a3 = fmaf(zdv.w, w1c[15], a3);
                    h1s[t] = siluf((a0 + a1) + (a2 + a3));
                }
                __syncthreads();  // h1 ready

                // ---------- L2: all 256 threads, lane-pair split ----------
                {
                    unsigned long long acc0 = 0ull, acc1 = 0ull;
#pragma unroll
                    for (int m = 0; m < 16; m++) {
                        unsigned long long p0, p1;
                        asm volatile("ld.shared.v2.u64 {%0,%1}, [%2];"
                                     : "=l"(p0), "=l"(p1) : "r"(hread + 16u * m));
                        FFMA2(acc0, p0, w2h[2 * m]);
                        FFMA2(acc1, p1, w2h[2 * m + 1]);
                    }
                    asm("add.rn.f32x2 %0, %1, %2;" : "=l"(acc0) : "l"(acc0), "l"(acc1));
                    float slo, shi;
                    asm("mov.b64 {%0,%1}, %2;" : "=f"(slo), "=f"(shi) : "l"(acc0));
                    float ssum = slo + shi;
                    ssum += __shfl_xor_sync(0xffffffffu, ssum, 1);
                    if (hh == 0) a2p[c2 + 4 * (c2 >> 3)] = siluf(ssum + b2c);
                }
                __syncthreads();  // a2 ready

                // ---------- L3: warps 0-3, 16 outputs x 8 partials ----------
                if (t < 128) {
                    unsigned long long q0, q1, q2, q3;
                    asm volatile("ld.shared.v2.u64 {%0,%1}, [%2];"
                                 : "=l"(q0), "=l"(q1) : "r"(a3base));
                    asm volatile("ld.shared.v2.u64 {%0,%1}, [%2];"
                                 : "=l"(q2), "=l"(q3) : "r"(a3base + 48u));
                    unsigned long long a3 = 0ull, a3b = 0ull;
                    FFMA2(a3,  q0, w3p[0]);
                    FFMA2(a3b, q1, w3p[1]);
                    FFMA2(a3,  q2, w3p[4]);
                    FFMA2(a3b, q3, w3p[5]);
                    asm volatile("ld.shared.v2.u64 {%0,%1}, [%2];"
                                 : "=l"(q0), "=l"(q1) : "r"(a3base + 16u));
                    asm volatile("ld.shared.v2.u64 {%0,%1}, [%2];"
                                 : "=l"(q2), "=l"(q3) : "r"(a3base + 64u));
                    FFMA2(a3,  q0, w3p[2]);
                    FFMA2(a3b, q1, w3p[3]);
                    FFMA2(a3,  q2, w3p[6]);
                    FFMA2(a3b, q3, w3p[7]);
                    asm("add.rn.f32x2 %0, %1, %2;" : "=l"(a3) : "l"(a3), "l"(a3b));
                    float plo, phi;
                    asm("mov.b64 {%0,%1}, %2;" : "=f"(plo), "=f"(phi) : "l"(a3));
                    float p = plo + phi;
                    p += __shfl_xor_sync(0xffffffffu, p, 1, 8);
                    p += __shfl_xor_sync(0xffffffffu, p, 2, 8);
                    p += __shfl_xor_sync(0xffffffffu, p, 4, 8);
                    if (gg == 0) dzs[oo] = p + b3o;
                }
                __syncthreads();  // dz ready

                // ---------- LN + state update: lanes 0-15 only, shfl-free ----------
                if (t < 16) {
                    const float4 d0 = ((const float4*)dzs)[0];
                    const float4 d1 = ((const float4*)dzs)[1];
                    const float4 d2 = ((const float4*)dzs)[2];
                    const float4 d3 = ((const float4*)dzs)[3];
                    const float dv = dzs[t];
                    float s0 = (d0.x + d0.y) + (d0.z + d0.w);
                    float s1 = (d1.x + d1.y) + (d1.z + d1.w);
                    float s2 = (d2.x + d2.y) + (d2.z + d2.w);
                    float s3 = (d3.x + d3.y) + (d3.z + d3.w);
                    float q0 = fmaf(d0.x, d0.x, d0.y * d0.y);
                    float q1 = fmaf(d0.z, d0.z, d0.w * d0.w);
                    q0 = fmaf(d1.x, d1.x, q0); q1 = fmaf(d1.y, d1.y, q1);
                    q0 = fmaf(d1.z, d1.z, q0); q1 = fmaf(d1.w, d1.w, q1);
                    q0 = fmaf(d2.x, d2.x, q0); q1 = fmaf(d2.y, d2.y, q1);
                    q0 = fmaf(d2.z, d2.z, q0); q1 = fmaf(d2.w, d2.w, q1);
                    q0 = fmaf(d3.x, d3.x, q0); q1 = fmaf(d3.y, d3.y, q1);
                    q0 = fmaf(d3.z, d3.z, q0); q1 = fmaf(d3.w, d3.w, q1);
                    const float mn = ((s0 + s1) + (s2 + s3)) * (1.f / 16.f);
                    const float vr = (q0 + q1) * (1.f / 16.f) - mn * mn;
                    const float kv = (dv - mn) * rsqrtf(vr + 1e-5f) * lgv + lbv;

                    float zin;
                    if (s == 0) {
                        k1 = kv;
                        zin = zc + hs * (0.2f * k1);
                    } else if (s == 1) {
                        k2 = kv;
                        zin = zc + hs * (0.075f * k1 + 0.225f * k2);
                    } else if (s == 2) {
                        k3 = kv;
                        zin = zc + hs * ((44.f/45.f)*k1 - (56.f/15.f)*k2 + (32.f/9.f)*k3);
                    } else if (s == 3) {
                        k4 = kv;
                        zin = zc + hs * ((19372.f/6561.f)*k1 - (25360.f/2187.f)*k2
                                       + (64448.f/6561.f)*k3 - (212.f/729.f)*k4);
                    } else if (s == 4) {
                        k5 = kv;
                        zin = zc + hs * ((9017.f/3168.f)*k1 - (355.f/33.f)*k2
                                       + (46732.f/5247.f)*k3 + (49.f/176.f)*k4
                                       - (5103.f/18656.f)*k5);
                    } else {
                        zc = zc + hs * ((35.f/384.f)*k1 + (500.f/1113.f)*k3
                                      + (125.f/192.f)*k4 - (2187.f/6784.f)*k5
                                      + (11.f/84.f)*kv);
                        zin = zc;
                        if (sub == KSUB - 1) zrow[(iv + 1) * DD + t] = zc;
                    }
                    zins[t] = zin;
                }
                __syncthreads();  // zin ready
            }
        }
    }
}

// ---------------------------------------------------------------------------
// Decoder stage 1: g2 = relu(relu(z W1 + b1) W2 + b2).
// 16-row tiles, 128 threads, 4 output columns per thread.
// ---------------------------------------------------------------------------
__global__ void __launch_bounds__(128)
dec1_kernel(const float* __restrict__ ztraj,
            const float* __restrict__ w1, const float* __restrict__ b1,
            const float* __restrict__ w2, const float* __restrict__ b2)
{
    __shared__ float zts[16 * 16];
    __shared__ float g1s[16 * 512];  // 32 KB
    const int t = threadIdx.x;
    const int row0 = blockIdx.x * 16;

    zts[t]       = ztraj[(size_t)row0 * 16 + t];
    zts[t + 128] = ztraj[(size_t)row0 * 16 + t + 128];

    {
        float w1r[4][16];
        float b1v[4];
#pragma unroll
        for (int q = 0; q < 4; q++) {
            const int c = t + 128 * q;
            b1v[q] = b1[c];
#pragma unroll
            for (int k = 0; k < 16; k++) w1r[q][k] = w1[k * 512 + c];
        }
        __syncthreads();

#pragma unroll
        for (int r = 0; r < 16; r++) {
            const float4* z4 = (const float4*)(zts + r * 16);
            const float4 z0 = z4[0], z1 = z4[1], z2 = z4[2], z3 = z4[3];
#pragma unroll
            for (int q = 0; q < 4; q++) {
                float a = b1v[q];
                a = fmaf(z0.x, w1r[q][0],  a);
                a = fmaf(z0.y, w1r[q][1],  a);
                a = fmaf(z0.z, w1r[q][2],  a);
                a = fmaf(z0.w, w1r[q][3],  a);
                a = fmaf(z1.x, w1r[q][4],  a);
                a = fmaf(z1.y, w1r[q][5],  a);
                a = fmaf(z1.z, w1r[q][6],  a);
                a = fmaf(z1.w, w1r[q][7],  a);
                a = fmaf(z2.x, w1r[q][8],  a);
                a = fmaf(z2.y, w1r[q][9],  a);
                a = fmaf(z2.z, w1r[q][10], a);
                a = fmaf(z2.w, w1r[q][11], a);
                a = fmaf(z3.x, w1r[q][12], a);
                a = fmaf(z3.y, w1r[q][13], a);
                a = fmaf(z3.z, w1r[q][14], a);
                a = fmaf(z3.w, w1r[q][15], a);
                g1s[r * 512 + t + 128 * q] = fmaxf(a, 0.f);
            }
        }
    }
    __syncthreads();

    float acc0[16], acc1[16], acc2[16], acc3[16];
    {
        const float bv0 = b2[t], bv1 = b2[t + 128],
                    bv2 = b2[t + 256], bv3 = b2[t + 384];
#pragma unroll
        for (int r = 0; r < 16; r++) {
            acc0[r] = bv0; acc1[r] = bv1; acc2[r] = bv2; acc3[r] = bv3;
        }
    }

    for (int j0 = 0; j0 < 512; j0 += 4) {
        float wv[4][4];
#pragma unroll
        for (int i = 0; i < 4; i++) {
            const float* wr = w2 + (size_t)(j0 + i) * 512 + t;
            wv[i][0] = wr[0];
            wv[i][1] = wr[128];
            wv[i][2] = wr[256];
            wv[i][3] = wr[384];
        }
#pragma unroll
        for (int r = 0; r < 16; r++) {
            const float4 gv = *(const float4*)(g1s + r * 512 + j0);
            acc0[r] = fmaf(gv.x, wv[0][0], acc0[r]);
            acc1[r] = fmaf(gv.x, wv[0][1], acc1[r]);
            acc2[r] = fmaf(gv.x, wv[0][2], acc2[r]);
            acc3[r] = fmaf(gv.x, wv[0][3], acc3[r]);
            acc0[r] = fmaf(gv.y, wv[1][0], acc0[r]);
            acc1[r] = fmaf(gv.y, wv[1][1], acc1[r]);
            acc2[r] = fmaf(gv.y, wv[1][2], acc2[r]);
            acc3[r] = fmaf(gv.y, wv[1][3], acc3[r]);
            acc0[r] = fmaf(gv.z, wv[2][0], acc0[r]);
            acc1[r] = fmaf(gv.z, wv[2][1], acc1[r]);
            acc2[r] = fmaf(gv.z, wv[2][2], acc2[r]);
            acc3[r] = fmaf(gv.z, wv[2][3], acc3[r]);
            acc0[r] = fmaf(gv.w, wv[3][0], acc0[r]);
            acc1[r] = fmaf(gv.w, wv[3][1], acc1[r]);
            acc2[r] = fmaf(gv.w, wv[3][2], acc2[r]);
            acc3[r] = fmaf(gv.w, wv[3][3], acc3[r]);
        }
    }
#pragma unroll
    for (int r = 0; r < 16; r++) {
        float* gr = g_g2 + (size_t)(row0 + r) * 512 + t;
        gr[0]   = fmaxf(acc0[r], 0.f);
        gr[128] = fmaxf(acc1[r], 0.f);
        gr[256] = fmaxf(acc2[r], 0.f);
        gr[384] = fmaxf(acc3[r], 0.f);
    }
}

// ---------------------------------------------------------------------------
// Decoder stage 2: xhat = g2 W3 + b3.
// 16-row tiles, 2 output columns per thread (cols t and t+128).
// ---------------------------------------------------------------------------
__global__ void __launch_bounds__(128)
dec2_kernel(const float* __restrict__ w3, const float* __restrict__ b3,
            float* __restrict__ out)
{
    __shared__ float g2s[16 * 512];  // 32 KB
    const int t = threadIdx.x;
    const int row0 = blockIdx.x * 16;
    const int c0 = t, c1 = t + 128;

#pragma unroll
    for (int i = 0; i < 64; i++)
        g2s[i * 128 + t] = g_g2[(size_t)row0 * 512 + i * 128 + t];
    __syncthreads();

    float acc0[16], acc1[16];
    const float bv0 = b3[c0], bv1 = b3[c1];
#pragma unroll
    for (int r = 0; r < 16; r++) { acc0[r] = bv0; acc1[r] = bv1; }

    for (int j0 = 0; j0 < 512; j0 += 4) {
        float wa0 = w3[(j0 + 0) * 256 + c0], wb0 = w3[(j0 + 0) * 256 + c1];
        float wa1 = w3[(j0 + 1) * 256 + c0], wb1 = w3[(j0 + 1) * 256 + c1];
        float wa2 = w3[(j0 + 2) * 256 + c0], wb2 = w3[(j0 + 2) * 256 + c1];
        float wa3 = w3[(j0 + 3) * 256 + c0], wb3 = w3[(j0 + 3) * 256 + c1];
#pragma unroll
        for (int r = 0; r < 16; r++) {
            const float4 gv = *(const float4*)(g2s + r * 512 + j0);
            acc0[r] = fmaf(gv.x, wa0, acc0[r]); acc1[r] = fmaf(gv.x, wb0, acc1[r]);
            acc0[r] = fmaf(gv.y, wa1, acc0[r]); acc1[r] = fmaf(gv.y, wb1, acc1[r]);
            acc0[r] = fmaf(gv.z, wa2, acc0[r]); acc1[r] = fmaf(gv.z, wb2, acc1[r]);
            acc0[r] = fmaf(gv.w, wa3, acc0[r]); acc1[r] = fmaf(gv.w, wb3, acc1[r]);
        }
    }
#pragma unroll
    for (int r = 0; r < 16; r++) {
        out[OFF_XHAT + (size_t)(row0 + r) * 256 + c0] = acc0[r];
        out[OFF_XHAT + (size_t)(row0 + r) * 256 + c1] = acc1[r];
    }
}

// ---------------------------------------------------------------------------
// zdiff = (z_traj[:,1:,:] - z_traj[:,:-1,:]) / dt
// ---------------------------------------------------------------------------
__global__ void zdiff_kernel(const float* __restrict__ tvec, float* __restrict__ out)
{
    const int idx = blockIdx.x * blockDim.x + threadIdx.x;
    const int total = BB * (LL - 1) * DD;
    if (idx >= total) return;
    const int o = idx & 15;
    const int rest = idx >> 4;
    const int i = rest % (LL - 1);
    const int b = rest / (LL - 1);
    const float dt = tvec[i + 1] - tvec[i];
    const float* zr = out + OFF_ZT + (size_t)b * (LL * DD);
    out[OFF_ZD + idx] = (zr[(i + 1) * DD + o] - zr[i * DD + o]) / dt;
}

// ---------------------------------------------------------------------------
extern "C" void kernel_launch(void* const* d_in, const int* in_sizes, int n_in,
                              void* d_out, int out_size)
{
    const float* x_seq  = (const float*)d_in[0];
    const float* tvec   = (const float*)d_in[1];
    const float* eps    = (const float*)d_in[2];
    const float* enc_w1 = (const float*)d_in[3];
    const float* enc_b1 = (const float*)d_in[4];
    const float* enc_w2 = (const float*)d_in[5];
    const float* enc_b2 = (const float*)d_in[6];
    const float* enc_w3 = (const float*)d_in[7];
    const float* enc_b3 = (const float*)d_in[8];
    const float* mu_w   = (const float*)d_in[9];
    const float* mu_b   = (const float*)d_in[10];
    const float* lv_w   = (const float*)d_in[11];
    const float* lv_b   = (const float*)d_in[12];
    const float* ode_w1 = (const float*)d_in[13];
    const float* ode_b1 = (const float*)d_in[14];
    const float* ode_w2 = (const float*)d_in[15];
    const float* ode_b2 = (const float*)d_in[16];
    const float* ode_w3 = (const float*)d_in[17];
    const float* ode_b3 = (const float*)d_in[18];
    const float* ln_g   = (const float*)d_in[19];
    const float* ln_b   = (const float*)d_in[20];
    const float* dec_w1 = (const float*)d_in[21];
    const float* dec_b1 = (const float*)d_in[22];
    const float* dec_w2 = (const float*)d_in[23];
    const float* dec_b2 = (const float*)d_in[24];
    const float* dec_w3 = (const float*)d_in[25];
    const float* dec_b3 = (const float*)d_in[26];
    float* out = (float*)d_out;

    enc_kernel<<<BB, 256>>>(x_seq, eps, enc_w1, enc_b1, enc_w2, enc_b2,
                            enc_w3, enc_b3, mu_w, mu_b, lv_w, lv_b, out);
    ode_kernel<<<BB, 256>>>(tvec, ode_w1, ode_b1, ode_w2, ode_b2,
                            ode_w3, ode_b3, ln_g, ln_b, out);
    zdiff_kernel<<<(BB * (LL - 1) * DD + 255) / 256, 256>>>(tvec, out);
    dec1_kernel<<<(BB * LL) / 16, 128>>>(out + OFF_ZT, dec_w1, dec_b1, dec_w2, dec_b2);
    dec2_kernel<<<(BB * LL) / 16, 128>>>(dec_w3, dec_b3, out);
}

// round 6
// speedup vs baseline: 1.1388x; 1.1388x over previous
#include <cuda_runtime.h>
#include <math.h>

#define BB 256
#define LL 200
#define NN 256
#define DD 16
#define KSUB 8

// Output layout: xhat | mu | logvar | z_traj | zdiff  (all float32)
#define OFF_XHAT 0
#define OFF_MU   (BB*LL*NN)
#define OFF_LV   (OFF_MU + BB*DD)
#define OFF_ZT   (OFF_LV + BB*DD)
#define OFF_ZD   (OFF_ZT + BB*LL*DD)

// decoder intermediate g2: 51200 x 512 fp32
__device__ float g_g2[51200 * 512];

__device__ __forceinline__ float siluf(float x) {
    return __fdividef(x, 1.f + __expf(-x));
}

__device__ __forceinline__ unsigned long long pack2(float lo, float hi) {
    unsigned long long r;
    asm("mov.b64 %0, {%1, %2};" : "=l"(r) : "f"(lo), "f"(hi));
    return r;
}

#define FFMA2(acc, a, b) \
    asm("fma.rn.f32x2 %0, %1, %2, %0;" : "+l"(acc) : "l"(a), "l"(b))

// ---------------------------------------------------------------------------
// Encoder: one CTA per batch row, 256 threads.
// ---------------------------------------------------------------------------
__global__ void __launch_bounds__(256)
enc_kernel(const float* __restrict__ x_seq,
           const float* __restrict__ eps,
           const float* __restrict__ w1, const float* __restrict__ b1,
           const float* __restrict__ w2, const float* __restrict__ b2,
           const float* __restrict__ w3, const float* __restrict__ b3,
           const float* __restrict__ muw, const float* __restrict__ mub,
           const float* __restrict__ lvw, const float* __restrict__ lvb,
           float* __restrict__ out)
{
    __shared__ float x0[256];
    __shared__ float h1[512];
    __shared__ float h2[256];
    __shared__ float h3[128];
    const int b = blockIdx.x;
    const int t = threadIdx.x;

    x0[t] = x_seq[(size_t)b * (LL * NN) + t];
    __syncthreads();

    for (int c = t; c < 512; c += 256) {
        float acc = b1[c];
#pragma unroll 8
        for (int j = 0; j < 256; j++) acc = fmaf(x0[j], w1[j * 512 + c], acc);
        h1[c] = fmaxf(acc, 0.f);
    }
    __syncthreads();

    {
        float acc = b2[t];
#pragma unroll 8
        for (int j = 0; j < 512; j++) acc = fmaf(h1[j], w2[j * 256 + t], acc);
        h2[t] = fmaxf(acc, 0.f);
    }
    __syncthreads();

    if (t < 128) {
        float acc = b3[t];
#pragma unroll 8
        for (int j = 0; j < 256; j++) acc = fmaf(h2[j], w3[j * 128 + t], acc);
        h3[t] = fmaxf(acc, 0.f);
    }
    __syncthreads();

    if (t < 16) {
        float m = mub[t];
        float lv = lvb[t];
#pragma unroll 8
        for (int j = 0; j < 128; j++) {
            m  = fmaf(h3[j], muw[j * 16 + t], m);
            lv = fmaf(h3[j], lvw[j * 16 + t], lv);
        }
        out[OFF_MU + b * DD + t] = m;
        out[OFF_LV + b * DD + t] = lv;
        float z0 = m + expf(0.5f * lv) * eps[b * DD + t];
        out[OFF_ZT + (size_t)b * (LL * DD) + t] = z0;
    }
}

// ---------------------------------------------------------------------------
// ODE integrator v4: one CTA per batch row, 128 threads (4 warps),
// TWO barriers per dopri stage.
//   Phase A (all): a2 = silu(W2^T h1 + b2), full W2 column in regs. BAR.
//   Phase B (per-warp redundant): L3 half-column + 1 shfl_xor -> dz[o];
//   LN via 4 shfl_xor(width16); per-lane k-state for own o; zin; L1 via
//   16-lane shfl broadcast -> h1s[t]. BAR.
// ---------------------------------------------------------------------------
__global__ void __launch_bounds__(128, 2)
ode_kernel(const float* __restrict__ tvec,
           const float* __restrict__ w1, const float* __restrict__ b1,
           const float* __restrict__ w2, const float* __restrict__ b2,
           const float* __restrict__ w3, const float* __restrict__ b3,
           const float* __restrict__ lng, const float* __restrict__ lnb,
           float* __restrict__ out)
{
    const int t    = threadIdx.x;
    const int b    = blockIdx.x;
    const int lane = t & 31;
    const int o    = lane & 15;   // phase-B output index
    const int hf   = lane >> 4;   // j-half for L3

    __shared__ __align__(16) float h1s[128];
    __shared__ __align__(16) float a2s[128];
    __shared__ __align__(16) float w3t[16 * 132];  // transposed, stride 132
    __shared__ float tvs[LL];

    // ---- W2 column t: 128 floats as 64 packed pairs ----
    unsigned long long w2h[64];
#pragma unroll
    for (int m = 0; m < 64; m++)
        w2h[m] = pack2(w2[(2 * m) * 128 + t], w2[(2 * m + 1) * 128 + t]);
    const float b2t = b2[t];

    // ---- W1 column t ----
    float w1c[16];
#pragma unroll
    for (int j = 0; j < 16; j++) w1c[j] = w1[j * 128 + t];
    const float b1t = b1[t];

    // ---- W3 transpose into smem: w3t[o][j] = w3[j][o] ----
    for (int i = t; i < 16 * 128; i += 128) {
        const int oo = i >> 7;
        const int j  = i & 127;
        w3t[oo * 132 + j] = w3[j * 16 + oo];
    }
    for (int i = t; i < LL; i += 128) tvs[i] = tvec[i];

    const float lgv = lng[o], lbv = lnb[o], b3o = b3[o];

    float* zrow = out + OFF_ZT + (size_t)b * (LL * DD);
    float zc = zrow[o];   // per-lane state for own o (replicated 8x)
    float k1 = 0.f, k2 = 0.f, k3 = 0.f, k4 = 0.f, k5 = 0.f;

    __syncthreads();  // w3t, tvs ready

    // ---- prologue: h1s(z0) ----
    {
        float acc = b1t;
#pragma unroll
        for (int j = 0; j < 16; j++) {
            float zj = __shfl_sync(0xffffffffu, zc, j, 16);
            acc = fmaf(zj, w1c[j], acc);
        }
        h1s[t] = siluf(acc);
    }
    __syncthreads();

    const unsigned h1b  = (unsigned)__cvta_generic_to_shared(h1s);
    const unsigned a2rb = (unsigned)__cvta_generic_to_shared(a2s) + 256u * (unsigned)hf;
    const unsigned w3b  = (unsigned)__cvta_generic_to_shared(w3t)
                        + ((unsigned)o * 132u + 64u * (unsigned)hf) * 4u;

    for (int iv = 0; iv < LL - 1; iv++) {
        const float hs = (tvs[iv + 1] - tvs[iv]) * (1.f / (float)KSUB);
        for (int sub = 0; sub < KSUB; sub++) {
#pragma unroll
            for (int s = 0; s < 6; s++) {
                // ---------- Phase A: a2[t] = silu(W2^T h1 + b2) ----------
                {
                    unsigned long long A0 = 0ull, A1 = 0ull, A2 = 0ull, A3 = 0ull;
#pragma unroll
                    for (int m = 0; m < 16; m++) {
                        unsigned long long p0, p1, p2, p3;
                        asm volatile("ld.shared.v2.u64 {%0,%1}, [%2];"
                                     : "=l"(p0), "=l"(p1) : "r"(h1b + 32u * m));
                        asm volatile("ld.shared.v2.u64 {%0,%1}, [%2];"
                                     : "=l"(p2), "=l"(p3) : "r"(h1b + 32u * m + 16u));
                        FFMA2(A0, p0, w2h[4 * m]);
                        FFMA2(A1, p1, w2h[4 * m + 1]);
                        FFMA2(A2, p2, w2h[4 * m + 2]);
                        FFMA2(A3, p3, w2h[4 * m + 3]);
                    }
                    asm("add.rn.f32x2 %0, %1, %2;" : "=l"(A0) : "l"(A0), "l"(A1));
                    asm("add.rn.f32x2 %0, %1, %2;" : "=l"(A2) : "l"(A2), "l"(A3));
                    asm("add.rn.f32x2 %0, %1, %2;" : "=l"(A0) : "l"(A0), "l"(A2));
                    float alo, ahi;
                    asm("mov.b64 {%0,%1}, %2;" : "=f"(alo), "=f"(ahi) : "l"(A0));
                    a2s[t] = siluf(alo + ahi + b2t);
                }
                __syncthreads();  // BAR1: a2 ready (also protects h1s WAR)

                // ---------- Phase B (warp-local): L3 + LN + state + L1 ----------
                {
                    unsigned long long B0 = 0ull, B1 = 0ull;
#pragma unroll
                    for (int m = 0; m < 16; m++) {
                        unsigned long long q0, q1, r0, r1;
                        asm volatile("ld.shared.v2.u64 {%0,%1}, [%2];"
                                     : "=l"(q0), "=l"(q1) : "r"(a2rb + 16u * m));
                        asm volatile("ld.shared.v2.u64 {%0,%1}, [%2];"
                                     : "=l"(r0), "=l"(r1) : "r"(w3b + 16u * m));
                        FFMA2(B0, q0, r0);
                        FFMA2(B1, q1, r1);
                    }
                    asm("add.rn.f32x2 %0, %1, %2;" : "=l"(B0) : "l"(B0), "l"(B1));
                    float plo, phi;
                    asm("mov.b64 {%0,%1}, %2;" : "=f"(plo), "=f"(phi) : "l"(B0));
                    float p = plo + phi;
                    p += __shfl_xor_sync(0xffffffffu, p, 16);  // combine j-halves
                    const float dv = p + b3o;

                    // LayerNorm over the 16 o's (width-16 butterflies, 2 chains)
                    float sm = dv, sq = dv * dv;
                    sm += __shfl_xor_sync(0xffffffffu, sm, 1, 16);
                    sq += __shfl_xor_sync(0xffffffffu, sq, 1, 16);
                    sm += __shfl_xor_sync(0xffffffffu, sm, 2, 16);
                    sq += __shfl_xor_sync(0xffffffffu, sq, 2, 16);
                    sm += __shfl_xor_sync(0xffffffffu, sm, 4, 16);
                    sq += __shfl_xor_sync(0xffffffffu, sq, 4, 16);
                    sm += __shfl_xor_sync(0xffffffffu, sm, 8, 16);
                    sq += __shfl_xor_sync(0xffffffffu, sq, 8, 16);
                    const float mn = sm * (1.f / 16.f);
                    const float vr = sq * (1.f / 16.f) - mn * mn;
                    const float kv = (dv - mn) * rsqrtf(vr + 1e-5f) * lgv + lbv;

                    float zin;
                    if (s == 0) {
                        k1 = kv;
                        zin = zc + hs * (0.2f * k1);
                    } else if (s == 1) {
                        k2 = kv;
                        zin = zc + hs * (0.075f * k1 + 0.225f * k2);
                    } else if (s == 2) {
                        k3 = kv;
                        zin = zc + hs * ((44.f/45.f)*k1 - (56.f/15.f)*k2 + (32.f/9.f)*k3);
                    } else if (s == 3) {
                        k4 = kv;
                        zin = zc + hs * ((19372.f/6561.f)*k1 - (25360.f/2187.f)*k2
                                       + (64448.f/6561.f)*k3 - (212.f/729.f)*k4);
                    } else if (s == 4) {
                        k5 = kv;
                        zin = zc + hs * ((9017.f/3168.f)*k1 - (355.f/33.f)*k2
                                       + (46732.f/5247.f)*k3 + (49.f/176.f)*k4
                                       - (5103.f/18656.f)*k5);
                    } else {
                        zc = zc + hs * ((35.f/384.f)*k1 + (500.f/1113.f)*k3
                                      + (125.f/192.f)*k4 - (2187.f/6784.f)*k5
                                      + (11.f/84.f)*kv);
                        zin = zc;
                    }

                    // L1: h1[t] = silu(W1^T zin + b1), zin broadcast in 16-lane seg
                    float acc = b1t;
#pragma unroll
                    for (int j = 0; j < 16; j++) {
                        float zj = __shfl_sync(0xffffffffu, zin, j, 16);
                        acc = fmaf(zj, w1c[j], acc);
                    }
                    h1s[t] = siluf(acc);

                    if (s == 5 && sub == KSUB - 1 && t < 16)
                        zrow[(iv + 1) * DD + o] = zc;
                }
                __syncthreads();  // BAR2: h1 ready (also protects a2s WAR)
            }
        }
    }
}

// ---------------------------------------------------------------------------
// Decoder stage 1: g2 = relu(relu(z W1 + b1) W2 + b2).
// 16-row tiles, 128 threads, 4 output columns per thread.
// ---------------------------------------------------------------------------
__global__ void __launch_bounds__(128)
dec1_kernel(const float* __restrict__ ztraj,
            const float* __restrict__ w1, const float* __restrict__ b1,
            const float* __restrict__ w2, const float* __restrict__ b2)
{
    __shared__ float zts[16 * 16];
    __shared__ float g1s[16 * 512];  // 32 KB
    const int t = threadIdx.x;
    const int row0 = blockIdx.x * 16;

    zts[t]       = ztraj[(size_t)row0 * 16 + t];
    zts[t + 128] = ztraj[(size_t)row0 * 16 + t + 128];

    {
        float w1r[4][16];
        float b1v[4];
#pragma unroll
        for (int q = 0; q < 4; q++) {
            const int c = t + 128 * q;
            b1v[q] = b1[c];
#pragma unroll
            for (int k = 0; k < 16; k++) w1r[q][k] = w1[k * 512 + c];
        }
        __syncthreads();

#pragma unroll
        for (int r = 0; r < 16; r++) {
            const float4* z4 = (const float4*)(zts + r * 16);
            const float4 z0 = z4[0], z1 = z4[1], z2 = z4[2], z3 = z4[3];
#pragma unroll
            for (int q = 0; q < 4; q++) {
                float a = b1v[q];
                a = fmaf(z0.x, w1r[q][0],  a);
                a = fmaf(z0.y, w1r[q][1],  a);
                a = fmaf(z0.z, w1r[q][2],  a);
                a = fmaf(z0.w, w1r[q][3],  a);
                a = fmaf(z1.x, w1r[q][4],  a);
                a = fmaf(z1.y, w1r[q][5],  a);
                a = fmaf(z1.z, w1r[q][6],  a);
                a = fmaf(z1.w, w1r[q][7],  a);
                a = fmaf(z2.x, w1r[q][8],  a);
                a = fmaf(z2.y, w1r[q][9],  a);
                a = fmaf(z2.z, w1r[q][10], a);
                a = fmaf(z2.w, w1r[q][11], a);
                a = fmaf(z3.x, w1r[q][12], a);
                a = fmaf(z3.y, w1r[q][13], a);
                a = fmaf(z3.z, w1r[q][14], a);
                a = fmaf(z3.w, w1r[q][15], a);
                g1s[r * 512 + t + 128 * q] = fmaxf(a, 0.f);
            }
        }
    }
    __syncthreads();

    float acc0[16], acc1[16], acc2[16], acc3[16];
    {
        const float bv0 = b2[t], bv1 = b2[t + 128],
                    bv2 = b2[t + 256], bv3 = b2[t + 384];
#pragma unroll
        for (int r = 0; r < 16; r++) {
            acc0[r] = bv0; acc1[r] = bv1; acc2[r] = bv2; acc3[r] = bv3;
        }
    }

    for (int j0 = 0; j0 < 512; j0 += 4) {
        float wv[4][4];
#pragma unroll
        for (int i = 0; i < 4; i++) {
            const float* wr = w2 + (size_t)(j0 + i) * 512 + t;
            wv[i][0] = wr[0];
            wv[i][1] = wr[128];
            wv[i][2] = wr[256];
            wv[i][3] = wr[384];
        }
#pragma unroll
        for (int r = 0; r < 16; r++) {
            const float4 gv = *(const float4*)(g1s + r * 512 + j0);
            acc0[r] = fmaf(gv.x, wv[0][0], acc0[r]);
            acc1[r] = fmaf(gv.x, wv[0][1], acc1[r]);
            acc2[r] = fmaf(gv.x, wv[0][2], acc2[r]);
            acc3[r] = fmaf(gv.x, wv[0][3], acc3[r]);
            acc0[r] = fmaf(gv.y, wv[1][0], acc0[r]);
            acc1[r] = fmaf(gv.y, wv[1][1], acc1[r]);
            acc2[r] = fmaf(gv.y, wv[1][2], acc2[r]);
            acc3[r] = fmaf(gv.y, wv[1][3], acc3[r]);
            acc0[r] = fmaf(gv.z, wv[2][0], acc0[r]);
            acc1[r] = fmaf(gv.z, wv[2][1], acc1[r]);
            acc2[r] = fmaf(gv.z, wv[2][2], acc2[r]);
            acc3[r] = fmaf(gv.z, wv[2][3], acc3[r]);
            acc0[r] = fmaf(gv.w, wv[3][0], acc0[r]);
            acc1[r] = fmaf(gv.w, wv[3][1], acc1[r]);
            acc2[r] = fmaf(gv.w, wv[3][2], acc2[r]);
            acc3[r] = fmaf(gv.w, wv[3][3], acc3[r]);
        }
    }
#pragma unroll
    for (int r = 0; r < 16; r++) {
        float* gr = g_g2 + (size_t)(row0 + r) * 512 + t;
        gr[0]   = fmaxf(acc0[r], 0.f);
        gr[128] = fmaxf(acc1[r], 0.f);
        gr[256] = fmaxf(acc2[r], 0.f);
        gr[384] = fmaxf(acc3[r], 0.f);
    }
}

// ---------------------------------------------------------------------------
// Decoder stage 2: xhat = g2 W3 + b3.
// 16-row tiles, 2 output columns per thread (cols t and t+128).
// ---------------------------------------------------------------------------
__global__ void __launch_bounds__(128)
dec2_kernel(const float* __restrict__ w3, const float* __restrict__ b3,
            float* __restrict__ out)
{
    __shared__ float g2s[16 * 512];  // 32 KB
    const int t = threadIdx.x;
    const int row0 = blockIdx.x * 16;
    const int c0 = t, c1 = t + 128;

#pragma unroll
    for (int i = 0; i < 64; i++)
        g2s[i * 128 + t] = g_g2[(size_t)row0 * 512 + i * 128 + t];
    __syncthreads();

    float acc0[16], acc1[16];
    const float bv0 = b3[c0], bv1 = b3[c1];
#pragma unroll
    for (int r = 0; r < 16; r++) { acc0[r] = bv0; acc1[r] = bv1; }

    for (int j0 = 0; j0 < 512; j0 += 4) {
        float wa0 = w3[(j0 + 0) * 256 + c0], wb0 = w3[(j0 + 0) * 256 + c1];
        float wa1 = w3[(j0 + 1) * 256 + c0], wb1 = w3[(j0 + 1) * 256 + c1];
        float wa2 = w3[(j0 + 2) * 256 + c0], wb2 = w3[(j0 + 2) * 256 + c1];
        float wa3 = w3[(j0 + 3) * 256 + c0], wb3 = w3[(j0 + 3) * 256 + c1];
#pragma unroll
        for (int r = 0; r < 16; r++) {
            const float4 gv = *(const float4*)(g2s + r * 512 + j0);
            acc0[r] = fmaf(gv.x, wa0, acc0[r]); acc1[r] = fmaf(gv.x, wb0, acc1[r]);
            acc0[r] = fmaf(gv.y, wa1, acc0[r]); acc1[r] = fmaf(gv.y, wb1, acc1[r]);
            acc0[r] = fmaf(gv.z, wa2, acc0[r]); acc1[r] = fmaf(gv.z, wb2, acc1[r]);
            acc0[r] = fmaf(gv.w, wa3, acc0[r]); acc1[r] = fmaf(gv.w, wb3, acc1[r]);
        }
    }
#pragma unroll
    for (int r = 0; r < 16; r++) {
        out[OFF_XHAT + (size_t)(row0 + r) * 256 + c0] = acc0[r];
        out[OFF_XHAT + (size_t)(row0 + r) * 256 + c1] = acc1[r];
    }
}

// ---------------------------------------------------------------------------
// zdiff = (z_traj[:,1:,:] - z_traj[:,:-1,:]) / dt
// ---------------------------------------------------------------------------
__global__ void zdiff_kernel(const float* __restrict__ tvec, float* __restrict__ out)
{
    const int idx = blockIdx.x * blockDim.x + threadIdx.x;
    const int total = BB * (LL - 1) * DD;
    if (idx >= total) return;
    const int o = idx & 15;
    const int rest = idx >> 4;
    const int i = rest % (LL - 1);
    const int b = rest / (LL - 1);
    const float dt = tvec[i + 1] - tvec[i];
    const float* zr = out + OFF_ZT + (size_t)b * (LL * DD);
    out[OFF_ZD + idx] = (zr[(i + 1) * DD + o] - zr[i * DD + o]) / dt;
}

// ---------------------------------------------------------------------------
extern "C" void kernel_launch(void* const* d_in, const int* in_sizes, int n_in,
                              void* d_out, int out_size)
{
    const float* x_seq  = (const float*)d_in[0];
    const float* tvec   = (const float*)d_in[1];
    const float* eps    = (const float*)d_in[2];
    const float* enc_w1 = (const float*)d_in[3];
    const float* enc_b1 = (const float*)d_in[4];
    const float* enc_w2 = (const float*)d_in[5];
    const float* enc_b2 = (const float*)d_in[6];
    const float* enc_w3 = (const float*)d_in[7];
    const float* enc_b3 = (const float*)d_in[8];
    const float* mu_w   = (const float*)d_in[9];
    const float* mu_b   = (const float*)d_in[10];
    const float* lv_w   = (const float*)d_in[11];
    const float* lv_b   = (const float*)d_in[12];
    const float* ode_w1 = (const float*)d_in[13];
    const float* ode_b1 = (const float*)d_in[14];
    const float* ode_w2 = (const float*)d_in[15];
    const float* ode_b2 = (const float*)d_in[16];
    const float* ode_w3 = (const float*)d_in[17];
    const float* ode_b3 = (const float*)d_in[18];
    const float* ln_g   = (const float*)d_in[19];
    const float* ln_b   = (const float*)d_in[20];
    const float* dec_w1 = (const float*)d_in[21];
    const float* dec_b1 = (const float*)d_in[22];
    const float* dec_w2 = (const float*)d_in[23];
    const float* dec_b2 = (const float*)d_in[24];
    const float* dec_w3 = (const float*)d_in[25];
    const float* dec_b3 = (const float*)d_in[26];
    float* out = (float*)d_out;

    enc_kernel<<<BB, 256>>>(x_seq, eps, enc_w1, enc_b1, enc_w2, enc_b2,
                            enc_w3, enc_b3, mu_w, mu_b, lv_w, lv_b, out);
    ode_kernel<<<BB, 128>>>(tvec, ode_w1, ode_b1, ode_w2, ode_b2,
                            ode_w3, ode_b3, ln_g, ln_b, out);
    zdiff_kernel<<<(BB * (LL - 1) * DD + 255) / 256, 256>>>(tvec, out);
    dec1_kernel<<<(BB * LL) / 16, 128>>>(out + OFF_ZT, dec_w1, dec_b1, dec_w2, dec_b2);
    dec2_kernel<<<(BB * LL) / 16, 128>>>(dec_w3, dec_b3, out);
}

// round 9
// speedup vs baseline: 1.4016x; 1.2308x over previous
#include <cuda_runtime.h>
#include <math.h>

#define BB 256
#define LL 200
#define NN 256
#define DD 16
#define KSUB 8

// Output layout: xhat | mu | logvar | z_traj | zdiff  (all float32)
#define OFF_XHAT 0
#define OFF_MU   (BB*LL*NN)
#define OFF_LV   (OFF_MU + BB*DD)
#define OFF_ZT   (OFF_LV + BB*DD)
#define OFF_ZD   (OFF_ZT + BB*LL*DD)

// decoder intermediate g2: 51200 x 512 fp32
__device__ float g_g2[51200 * 512];

__device__ __forceinline__ float siluf(float x) {
    return __fdividef(x, 1.f + __expf(-x));
}

__device__ __forceinline__ unsigned long long pack2(float lo, float hi) {
    unsigned long long r;
    asm("mov.b64 %0, {%1, %2};" : "=l"(r) : "f"(lo), "f"(hi));
    return r;
}

// non-volatile: pure arithmetic, compiler may schedule freely
#define FFMA2(acc, a, b) \
    asm("fma.rn.f32x2 %0, %1, %2, %0;" : "+l"(acc) : "l"(a), "l"(b))
#define FADD2(d, a, b) \
    asm("add.rn.f32x2 %0, %1, %2;" : "=l"(d) : "l"(a), "l"(b))

// ---------------------------------------------------------------------------
// Encoder: one CTA per batch row, 256 threads.
// ---------------------------------------------------------------------------
__global__ void __launch_bounds__(256)
enc_kernel(const float* __restrict__ x_seq,
           const float* __restrict__ eps,
           const float* __restrict__ w1, const float* __restrict__ b1,
           const float* __restrict__ w2, const float* __restrict__ b2,
           const float* __restrict__ w3, const float* __restrict__ b3,
           const float* __restrict__ muw, const float* __restrict__ mub,
           const float* __restrict__ lvw, const float* __restrict__ lvb,
           float* __restrict__ out)
{
    __shared__ float x0[256];
    __shared__ float h1[512];
    __shared__ float h2[256];
    __shared__ float h3[128];
    const int b = blockIdx.x;
    const int t = threadIdx.x;

    x0[t] = x_seq[(size_t)b * (LL * NN) + t];
    __syncthreads();

    for (int c = t; c < 512; c += 256) {
        float acc = b1[c];
#pragma unroll 8
        for (int j = 0; j < 256; j++) acc = fmaf(x0[j], w1[j * 512 + c], acc);
        h1[c] = fmaxf(acc, 0.f);
    }
    __syncthreads();

    {
        float acc = b2[t];
#pragma unroll 8
        for (int j = 0; j < 512; j++) acc = fmaf(h1[j], w2[j * 256 + t], acc);
        h2[t] = fmaxf(acc, 0.f);
    }
    __syncthreads();

    if (t < 128) {
        float acc = b3[t];
#pragma unroll 8
        for (int j = 0; j < 256; j++) acc = fmaf(h2[j], w3[j * 128 + t], acc);
        h3[t] = fmaxf(acc, 0.f);
    }
    __syncthreads();

    if (t < 16) {
        float m = mub[t];
        float lv = lvb[t];
#pragma unroll 8
        for (int j = 0; j < 128; j++) {
            m  = fmaf(h3[j], muw[j * 16 + t], m);
            lv = fmaf(h3[j], lvw[j * 16 + t], lv);
        }
        out[OFF_MU + b * DD + t] = m;
        out[OFF_LV + b * DD + t] = lv;
        float z0 = m + expf(0.5f * lv) * eps[b * DD + t];
        out[OFF_ZT + (size_t)b * (LL * DD) + t] = z0;
    }
}

// ---------------------------------------------------------------------------
// ODE integrator v6: one CTA per batch row, 128 threads (4 warps),
// TWO barriers per dopri stage. All weights register-resident:
// W2 column (64 packed), W3 half-column (32 packed), W1 column (16).
// All smem reads are plain C++ vector loads (pipelineable LDS).
//   Phase A (all): a2[t] = silu(W2^T h1 + b2). BAR.
//   Phase B (per-warp redundant): L3 half + shfl_xor(16) -> dz[o];
//   LN (4-deep interleaved shfl); per-lane state; L1 via 16-lane shfl. BAR.
// ---------------------------------------------------------------------------
__global__ void __launch_bounds__(128, 2)
ode_kernel(const float* __restrict__ tvec,
           const float* __restrict__ w1, const float* __restrict__ b1,
           const float* __restrict__ w2, const float* __restrict__ b2,
           const float* __restrict__ w3, const float* __restrict__ b3,
           const float* __restrict__ lng, const float* __restrict__ lnb,
           float* __restrict__ out)
{
    const int t    = threadIdx.x;
    const int b    = blockIdx.x;
    const int lane = t & 31;
    const int o    = lane & 15;   // phase-B output index
    const int hf   = lane >> 4;   // j-half for L3

    __shared__ __align__(16) float h1s[128];
    __shared__ __align__(16) float a2s[128];
    __shared__ float tvs[LL];

    // ---- W2 column t: 128 floats as 64 packed pairs ----
    unsigned long long w2h[64];
#pragma unroll
    for (int m = 0; m < 64; m++)
        w2h[m] = pack2(w2[(2 * m) * 128 + t], w2[(2 * m + 1) * 128 + t]);
    const float b2t = b2[t];

    // ---- W1 column t ----
    float w1c[16];
#pragma unroll
    for (int j = 0; j < 16; j++) w1c[j] = w1[j * 128 + t];
    const float b1t = b1[t];

    // ---- W3 half-column for (o, hf): 64 j's as 32 packed pairs ----
    unsigned long long w3p[32];
#pragma unroll
    for (int i = 0; i < 32; i++) {
        const int j = 64 * hf + 2 * i;
        w3p[i] = pack2(w3[j * 16 + o], w3[(j + 1) * 16 + o]);
    }
    const float b3o = b3[o];
    const float lgv = lng[o], lbv = lnb[o];

    for (int i = t; i < LL; i += 128) tvs[i] = tvec[i];

    float* zrow = out + OFF_ZT + (size_t)b * (LL * DD);
    float zc = zrow[o];   // per-lane state for own o (replicated 8x per CTA)
    float k1 = 0.f, k2 = 0.f, k3 = 0.f, k4 = 0.f, k5 = 0.f;

    __syncthreads();  // tvs ready

    // ---- prologue: h1s(z0) ----
    {
        float acc = b1t;
#pragma unroll
        for (int j = 0; j < 16; j++) {
            float zj = __shfl_sync(0xffffffffu, zc, j, 16);
            acc = fmaf(zj, w1c[j], acc);
        }
        h1s[t] = siluf(acc);
    }
    __syncthreads();

    const ulonglong2* __restrict__ h1v = (const ulonglong2*)h1s;
    const ulonglong2* __restrict__ a2v = (const ulonglong2*)(a2s + 64 * hf);

    for (int iv = 0; iv < LL - 1; iv++) {
        const float hs = (tvs[iv + 1] - tvs[iv]) * (1.f / (float)KSUB);
        for (int sub = 0; sub < KSUB; sub++) {
#pragma unroll
            for (int s = 0; s < 6; s++) {
                // ---------- Phase A: a2[t] = silu(W2^T h1 + b2) ----------
                {
                    unsigned long long A0 = 0ull, A1 = 0ull, A2 = 0ull, A3 = 0ull;
#pragma unroll
                    for (int m = 0; m < 16; m++) {
                        const ulonglong2 p = h1v[2 * m];
                        const ulonglong2 q = h1v[2 * m + 1];
                        FFMA2(A0, p.x, w2h[4 * m]);
                        FFMA2(A1, p.y, w2h[4 * m + 1]);
                        FFMA2(A2, q.x, w2h[4 * m + 2]);
                        FFMA2(A3, q.y, w2h[4 * m + 3]);
                    }
                    unsigned long long S0, S1, S;
                    FADD2(S0, A0, A1);
                    FADD2(S1, A2, A3);
                    FADD2(S, S0, S1);
                    float alo, ahi;
                    asm("mov.b64 {%0,%1}, %2;" : "=f"(alo), "=f"(ahi) : "l"(S));
                    a2s[t] = siluf(alo + ahi + b2t);
                }
                __syncthreads();  // BAR1: a2 ready

                // ---------- Phase B (warp-local): L3 + LN + state + L1 ----------
                {
                    unsigned long long B0 = 0ull, B1 = 0ull, B2 = 0ull, B3 = 0ull;
#pragma unroll
                    for (int m = 0; m < 8; m++) {
                        const ulonglong2 p = a2v[2 * m];
                        const ulonglong2 q = a2v[2 * m + 1];
                        FFMA2(B0, p.x, w3p[4 * m]);
                        FFMA2(B1, p.y, w3p[4 * m + 1]);
                        FFMA2(B2, q.x, w3p[4 * m + 2]);
                        FFMA2(B3, q.y, w3p[4 * m + 3]);
                    }
                    unsigned long long T0, T1, T;
                    FADD2(T0, B0, B1);
                    FADD2(T1, B2, B3);
                    FADD2(T, T0, T1);
                    float plo, phi;
                    asm("mov.b64 {%0,%1}, %2;" : "=f"(plo), "=f"(phi) : "l"(T));
                    float p = plo + phi;
                    p += __shfl_xor_sync(0xffffffffu, p, 16);  // combine j-halves
                    const float dv = p + b3o;

                    // LayerNorm over 16 o's: two interleaved 4-deep chains
                    float sm = dv, sq = dv * dv;
                    sm += __shfl_xor_sync(0xffffffffu, sm, 1, 16);
                    sq += __shfl_xor_sync(0xffffffffu, sq, 1, 16);
                    sm += __shfl_xor_sync(0xffffffffu, sm, 2, 16);
                    sq += __shfl_xor_sync(0xffffffffu, sq, 2, 16);
                    sm += __shfl_xor_sync(0xffffffffu, sm, 4, 16);
                    sq += __shfl_xor_sync(0xffffffffu, sq, 4, 16);
                    sm += __shfl_xor_sync(0xffffffffu, sm, 8, 16);
                    sq += __shfl_xor_sync(0xffffffffu, sq, 8, 16);
                    const float mn = sm * (1.f / 16.f);
                    const float vr = sq * (1.f / 16.f) - mn * mn;
                    const float kv = (dv - mn) * rsqrtf(vr + 1e-5f) * lgv + lbv;

                    float zin;
                    if (s == 0) {
                        k1 = kv;
                        zin = zc + hs * (0.2f * k1);
                    } else if (s == 1) {
                        k2 = kv;
                        zin = zc + hs * (0.075f * k1 + 0.225f * k2);
                    } else if (s == 2) {
                        k3 = kv;
                        zin = zc + hs * ((44.f/45.f)*k1 - (56.f/15.f)*k2 + (32.f/9.f)*k3);
                    } else if (s == 3) {
                        k4 = kv;
                        zin = zc + hs * ((19372.f/6561.f)*k1 - (25360.f/2187.f)*k2
                                       + (64448.f/6561.f)*k3 - (212.f/729.f)*k4);
                    } else if (s == 4) {
                        k5 = kv;
                        zin = zc + hs * ((9017.f/3168.f)*k1 - (355.f/33.f)*k2
                                       + (46732.f/5247.f)*k3 + (49.f/176.f)*k4
                                       - (5103.f/18656.f)*k5);
                    } else {
                        zc = zc + hs * ((35.f/384.f)*k1 + (500.f/1113.f)*k3
                                      + (125.f/192.f)*k4 - (2187.f/6784.f)*k5
                                      + (11.f/84.f)*kv);
                        zin = zc;
                    }

                    // L1: h1[t] = silu(W1^T zin + b1); zin broadcast within 16-lane seg
                    float acc = b1t;
#pragma unroll
                    for (int j = 0; j < 16; j++) {
                        float zj = __shfl_sync(0xffffffffu, zin, j, 16);
                        acc = fmaf(zj, w1c[j], acc);
                    }
                    h1s[t] = siluf(acc);

                    if (s == 5 && sub == KSUB - 1 && t < 16)
                        zrow[(iv + 1) * DD + o] = zc;
                }
                __syncthreads();  // BAR2: h1 ready / a2 WAR protected
            }
        }
    }
}

// ---------------------------------------------------------------------------
// Decoder stage 1: g2 = relu(relu(z W1 + b1) W2 + b2).
// 16-row tiles, 128 threads, 4 output columns per thread.
// ---------------------------------------------------------------------------
__global__ void __launch_bounds__(128)
dec1_kernel(const float* __restrict__ ztraj,
            const float* __restrict__ w1, const float* __restrict__ b1,
            const float* __restrict__ w2, const float* __restrict__ b2)
{
    __shared__ float zts[16 * 16];
    __shared__ float g1s[16 * 512];  // 32 KB
    const int t = threadIdx.x;
    const int row0 = blockIdx.x * 16;

    zts[t]       = ztraj[(size_t)row0 * 16 + t];
    zts[t + 128] = ztraj[(size_t)row0 * 16 + t + 128];

    {
        float w1r[4][16];
        float b1v[4];
#pragma unroll
        for (int q = 0; q < 4; q++) {
            const int c = t + 128 * q;
            b1v[q] = b1[c];
#pragma unroll
            for (int k = 0; k < 16; k++) w1r[q][k] = w1[k * 512 + c];
        }
        __syncthreads();

#pragma unroll
        for (int r = 0; r < 16; r++) {
            const float4* z4 = (const float4*)(zts + r * 16);
            const float4 z0 = z4[0], z1 = z4[1], z2 = z4[2], z3 = z4[3];
#pragma unroll
            for (int q = 0; q < 4; q++) {
                float a = b1v[q];
                a = fmaf(z0.x, w1r[q][0],  a);
                a = fmaf(z0.y, w1r[q][1],  a);
                a = fmaf(z0.z, w1r[q][2],  a);
                a = fmaf(z0.w, w1r[q][3],  a);
                a = fmaf(z1.x, w1r[q][4],  a);
                a = fmaf(z1.y, w1r[q][5],  a);
                a = fmaf(z1.z, w1r[q][6],  a);
                a = fmaf(z1.w, w1r[q][7],  a);
                a = fmaf(z2.x, w1r[q][8],  a);
                a = fmaf(z2.y, w1r[q][9],  a);
                a = fmaf(z2.z, w1r[q][10], a);
                a = fmaf(z2.w, w1r[q][11], a);
                a = fmaf(z3.x, w1r[q][12], a);
                a = fmaf(z3.y, w1r[q][13], a);
                a = fmaf(z3.z, w1r[q][14], a);
                a = fmaf(z3.w, w1r[q][15], a);
                g1s[r * 512 + t + 128 * q] = fmaxf(a, 0.f);
            }
        }
    }
    __syncthreads();

    float acc0[16], acc1[16], acc2[16], acc3[16];
    {
        const float bv0 = b2[t], bv1 = b2[t + 128],
                    bv2 = b2[t + 256], bv3 = b2[t + 384];
#pragma unroll
        for (int r = 0; r < 16; r++) {
            acc0[r] = bv0; acc1[r] = bv1; acc2[r] = bv2; acc3[r] = bv3;
        }
    }

    for (int j0 = 0; j0 < 512; j0 += 4) {
        float wv[4][4];
#pragma unroll
        for (int i = 0; i < 4; i++) {
            const float* wr = w2 + (size_t)(j0 + i) * 512 + t;
            wv[i][0] = wr[0];
            wv[i][1] = wr[128];
            wv[i][2] = wr[256];
            wv[i][3] = wr[384];
        }
#pragma unroll
        for (int r = 0; r < 16; r++) {
            const float4 gv = *(const float4*)(g1s + r * 512 + j0);
            acc0[r] = fmaf(gv.x, wv[0][0], acc0[r]);
            acc1[r] = fmaf(gv.x, wv[0][1], acc1[r]);
            acc2[r] = fmaf(gv.x, wv[0][2], acc2[r]);
            acc3[r] = fmaf(gv.x, wv[0][3], acc3[r]);
            acc0[r] = fmaf(gv.y, wv[1][0], acc0[r]);
            acc1[r] = fmaf(gv.y, wv[1][1], acc1[r]);
            acc2[r] = fmaf(gv.y, wv[1][2], acc2[r]);
            acc3[r] = fmaf(gv.y, wv[1][3], acc3[r]);
            acc0[r] = fmaf(gv.z, wv[2][0], acc0[r]);
            acc1[r] = fmaf(gv.z, wv[2][1], acc1[r]);
            acc2[r] = fmaf(gv.z, wv[2][2], acc2[r]);
            acc3[r] = fmaf(gv.z, wv[2][3], acc3[r]);
            acc0[r] = fmaf(gv.w, wv[3][0], acc0[r]);
            acc1[r] = fmaf(gv.w, wv[3][1], acc1[r]);
            acc2[r] = fmaf(gv.w, wv[3][2], acc2[r]);
            acc3[r] = fmaf(gv.w, wv[3][3], acc3[r]);
        }
    }
#pragma unroll
    for (int r = 0; r < 16; r++) {
        float* gr = g_g2 + (size_t)(row0 + r) * 512 + t;
        gr[0]   = fmaxf(acc0[r], 0.f);
        gr[128] = fmaxf(acc1[r], 0.f);
        gr[256] = fmaxf(acc2[r], 0.f);
        gr[384] = fmaxf(acc3[r], 0.f);
    }
}

// ---------------------------------------------------------------------------
// Decoder stage 2: xhat = g2 W3 + b3.
// 16-row tiles, 2 output columns per thread (cols t and t+128).
// ---------------------------------------------------------------------------
__global__ void __launch_bounds__(128)
dec2_kernel(const float* __restrict__ w3, const float* __restrict__ b3,
            float* __restrict__ out)
{
    __shared__ float g2s[16 * 512];  // 32 KB
    const int t = threadIdx.x;
    const int row0 = blockIdx.x * 16;
    const int c0 = t, c1 = t + 128;

#pragma unroll
    for (int i = 0; i < 64; i++)
        g2s[i * 128 + t] = g_g2[(size_t)row0 * 512 + i * 128 + t];
    __syncthreads();

    float acc0[16], acc1[16];
    const float bv0 = b3[c0], bv1 = b3[c1];
#pragma unroll
    for (int r = 0; r < 16; r++) { acc0[r] = bv0; acc1[r] = bv1; }

    for (int j0 = 0; j0 < 512; j0 += 4) {
        float wa0 = w3[(j0 + 0) * 256 + c0], wb0 = w3[(j0 + 0) * 256 + c1];
        float wa1 = w3[(j0 + 1) * 256 + c0], wb1 = w3[(j0 + 1) * 256 + c1];
        float wa2 = w3[(j0 + 2) * 256 + c0], wb2 = w3[(j0 + 2) * 256 + c1];
        float wa3 = w3[(j0 + 3) * 256 + c0], wb3 = w3[(j0 + 3) * 256 + c1];
#pragma unroll
        for (int r = 0; r < 16; r++) {
            const float4 gv = *(const float4*)(g2s + r * 512 + j0);
            acc0[r] = fmaf(gv.x, wa0, acc0[r]); acc1[r] = fmaf(gv.x, wb0, acc1[r]);
            acc0[r] = fmaf(gv.y, wa1, acc0[r]); acc1[r] = fmaf(gv.y, wb1, acc1[r]);
            acc0[r] = fmaf(gv.z, wa2, acc0[r]); acc1[r] = fmaf(gv.z, wb2, acc1[r]);
            acc0[r] = fmaf(gv.w, wa3, acc0[r]); acc1[r] = fmaf(gv.w, wb3, acc1[r]);
        }
    }
#pragma unroll
    for (int r = 0; r < 16; r++) {
        out[OFF_XHAT + (size_t)(row0 + r) * 256 + c0] = acc0[r];
        out[OFF_XHAT + (size_t)(row0 + r) * 256 + c1] = acc1[r];
    }
}

// ---------------------------------------------------------------------------
// zdiff = (z_traj[:,1:,:] - z_traj[:,:-1,:]) / dt
// ---------------------------------------------------------------------------
__global__ void zdiff_kernel(const float* __restrict__ tvec, float* __restrict__ out)
{
    const int idx = blockIdx.x * blockDim.x + threadIdx.x;
    const int total = BB * (LL - 1) * DD;
    if (idx >= total) return;
    const int o = idx & 15;
    const int rest = idx >> 4;
    const int i = rest % (LL - 1);
    const int b = rest / (LL - 1);
    const float dt = tvec[i + 1] - tvec[i];
    const float* zr = out + OFF_ZT + (size_t)b * (LL * DD);
    out[OFF_ZD + idx] = (zr[(i + 1) * DD + o] - zr[i * DD + o]) / dt;
}

// ---------------------------------------------------------------------------
extern "C" void kernel_launch(void* const* d_in, const int* in_sizes, int n_in,
                              void* d_out, int out_size)
{
    const float* x_seq  = (const float*)d_in[0];
    const float* tvec   = (const float*)d_in[1];
    const float* eps    = (const float*)d_in[2];
    const float* enc_w1 = (const float*)d_in[3];
    const float* enc_b1 = (const float*)d_in[4];
    const float* enc_w2 = (const float*)d_in[5];
    const float* enc_b2 = (const float*)d_in[6];
    const float* enc_w3 = (const float*)d_in[7];
    const float* enc_b3 = (const float*)d_in[8];
    const float* mu_w   = (const float*)d_in[9];
    const float* mu_b   = (const float*)d_in[10];
    const float* lv_w   = (const float*)d_in[11];
    const float* lv_b   = (const float*)d_in[12];
    const float* ode_w1 = (const float*)d_in[13];
    const float* ode_b1 = (const float*)d_in[14];
    const float* ode_w2 = (const float*)d_in[15];
    const float* ode_b2 = (const float*)d_in[16];
    const float* ode_w3 = (const float*)d_in[17];
    const float* ode_b3 = (const float*)d_in[18];
    const float* ln_g   = (const float*)d_in[19];
    const float* ln_b   = (const float*)d_in[20];
    const float* dec_w1 = (const float*)d_in[21];
    const float* dec_b1 = (const float*)d_in[22];
    const float* dec_w2 = (const float*)d_in[23];
    const float* dec_b2 = (const float*)d_in[24];
    const float* dec_w3 = (const float*)d_in[25];
    const float* dec_b3 = (const float*)d_in[26];
    float* out = (float*)d_out;

    enc_kernel<<<BB, 256>>>(x_seq, eps, enc_w1, enc_b1, enc_w2, enc_b2,
                            enc_w3, enc_b3, mu_w, mu_b, lv_w, lv_b, out);
    ode_kernel<<<BB, 128>>>(tvec, ode_w1, ode_b1, ode_w2, ode_b2,
                            ode_w3, ode_b3, ln_g, ln_b, out);
    zdiff_kernel<<<(BB * (LL - 1) * DD + 255) / 256, 256>>>(tvec, out);
    dec1_kernel<<<(BB * LL) / 16, 128>>>(out + OFF_ZT, dec_w1, dec_b1, dec_w2, dec_b2);
    dec2_kernel<<<(BB * LL) / 16, 128>>>(dec_w3, dec_b3, out);
}